// round 11
// baseline (speedup 1.0000x reference)
#include <cuda_runtime.h>
#include <cuda_bf16.h>
#include <cstdint>
#include <math.h>

#define NPTS 8192
#define DEMB 1024
#define NT   64            // 128-wide tiles per dim
#define NTILES 2080        // NT*(NT+1)/2 upper-triangular tiles
#define NCLS  128
#define CCAP  256          // class list capacity
#define PCAP  128          // posmine per-class cap (statistical max ~90)

// ---------------- scratch (device globals: no allocations allowed) ----------
__device__ __align__(128) __nv_bfloat16 g_hi[(size_t)NPTS * DEMB];   // 16 MB
__device__ __align__(128) __nv_bfloat16 g_lo[(size_t)NPTS * DEMB];   // 16 MB
__device__ __align__(128) float         g_sq[NPTS];
__device__ __align__(128) unsigned char g_tgt[NPTS];
__device__ __align__(128) int           g_ccnt[NCLS];
__device__ __align__(128) int           g_clist[NCLS * CCAP];
__device__ __align__(128) unsigned long long g_posk[NPTS];
__device__ __align__(128) unsigned long long g_hard[NPTS];
__device__ __align__(128) unsigned long long g_semi[NPTS];
__device__ __align__(128) float         g_dpf[NPTS];
__device__ __align__(128) int           g_pos[NPTS];
__device__ __align__(128) float         g_loss[NPTS];

// ---------------- ptx helpers ----------------------------------------------
__device__ __forceinline__ uint32_t smem_u32(const void* p) {
    uint32_t a;
    asm("{ .reg .u64 t; cvta.to.shared.u64 t, %1; cvt.u32.u64 %0, t; }"
        : "=r"(a) : "l"(p));
    return a;
}

__device__ __forceinline__ void cp16(uint32_t s, const void* g) {
    asm volatile("cp.async.cg.shared.global [%0], [%1], 16;" :: "r"(s), "l"(g));
}
__device__ __forceinline__ void cp_commit() {
    asm volatile("cp.async.commit_group;" ::: "memory");
}

__device__ __forceinline__ void ldsm4(uint32_t addr, uint32_t* r) {
    asm volatile("ldmatrix.sync.aligned.m8n8.x4.shared.b16 {%0,%1,%2,%3}, [%4];"
        : "=r"(r[0]), "=r"(r[1]), "=r"(r[2]), "=r"(r[3]) : "r"(addr));
}

__device__ __forceinline__ void mma16816(float* c, const uint32_t* a, const uint32_t* b) {
    asm volatile(
        "mma.sync.aligned.m16n8k16.row.col.f32.bf16.bf16.f32 "
        "{%0,%1,%2,%3},{%4,%5,%6,%7},{%8,%9},{%0,%1,%2,%3};"
        : "+f"(c[0]), "+f"(c[1]), "+f"(c[2]), "+f"(c[3])
        : "r"(a[0]), "r"(a[1]), "r"(a[2]), "r"(a[3]), "r"(b[0]), "r"(b[1]));
}

// ---------------- phase 0: convert to hi/lo bf16 split ---------------------
__global__ void __launch_bounds__(256) conv_kernel(const float* __restrict__ emb) {
    size_t idx = (size_t)blockIdx.x * 256 + threadIdx.x;
    float e = emb[idx];
    __nv_bfloat16 h = __float2bfloat16(e);
    g_hi[idx] = h;
    g_lo[idx] = __float2bfloat16(e - __bfloat162float(h));
}

// ---------------- phase 0b: row squared norms + target u8 + ccnt zero ------
__global__ void __launch_bounds__(256) sq_kernel(const float* __restrict__ emb,
                                                 const int* __restrict__ tgt) {
    if (blockIdx.x == 0 && threadIdx.x < NCLS) g_ccnt[threadIdx.x] = 0;
    int row = blockIdx.x * 8 + (threadIdx.x >> 5);
    int lid = threadIdx.x & 31;
    const float4* r4 = (const float4*)(emb + (size_t)row * DEMB);
    float s = 0.f;
#pragma unroll
    for (int k = 0; k < 8; k++) {
        float4 v = r4[lid + k * 32];
        s += v.x * v.x + v.y * v.y + v.z * v.z + v.w * v.w;
    }
#pragma unroll
    for (int o = 16; o; o >>= 1) s += __shfl_down_sync(0xffffffffu, s, o);
    if (lid == 0) {
        g_sq[row] = s;
        g_tgt[row] = (unsigned char)tgt[row];
    }
}

// ---------------- phase 0c: class lists + key init --------------------------
__global__ void __launch_bounds__(256) clsbuild_kernel(const int* __restrict__ tgt) {
    int i = blockIdx.x * 256 + threadIdx.x;
    g_posk[i] = 0ull;
    g_hard[i] = ~0ull;
    g_semi[i] = ~0ull;
    int c = tgt[i];
    int p = atomicAdd(&g_ccnt[c], 1);
    if (p < CCAP) g_clist[c * CCAP + p] = i;
}

// ---------------- phase 0d: hardest positive per anchor (fp32, per class) --
// One CTA per class. 16x16 thread grid, 4x4 register tile per thread ->
// full 64x64 pair superblock with ALL 256 threads active; superblock loop
// covers cnt up to PCAP. key = (bits(d)<<32) | (NPTS-1-j): atomicMax =
// max distance, min index on tie.
__global__ void __launch_bounds__(256) posmine_kernel(const float* __restrict__ emb) {
    __shared__ float s_a[64][68];
    __shared__ float s_b[64][68];
    __shared__ int   s_idx[PCAP];
    const int c   = blockIdx.x;
    const int tid = threadIdx.x;
    const int tx  = tid & 15;          // b-block
    const int ty  = tid >> 4;          // a-block
    int cnt = g_ccnt[c];
    if (cnt > PCAP) cnt = PCAP;
    for (int m = tid; m < cnt; m += 256) s_idx[m] = g_clist[c * CCAP + m];
    __syncthreads();

    const int nsb = (cnt + 63) >> 6;

    for (int sa = 0; sa < nsb; ++sa) {
        for (int sb = 0; sb < nsb; ++sb) {
            float acc[4][4];
#pragma unroll
            for (int i = 0; i < 4; i++)
#pragma unroll
                for (int j = 0; j < 4; j++) acc[i][j] = 0.f;

            for (int kc = 0; kc < 16; ++kc) {
                __syncthreads();
                // stage 64 a-rows and 64 b-rows of this k-chunk (64 floats)
                for (int q = tid; q < 64 * 16; q += 256) {
                    const int r = q >> 4, f = q & 15;
                    const int ra = sa * 64 + r;
                    float4 va = make_float4(0.f, 0.f, 0.f, 0.f);
                    if (ra < cnt)
                        va = *(const float4*)(emb + (size_t)s_idx[ra] * DEMB + kc * 64 + f * 4);
                    *(float4*)&s_a[r][f * 4] = va;
                    const int rb = sb * 64 + r;
                    float4 vb = make_float4(0.f, 0.f, 0.f, 0.f);
                    if (rb < cnt)
                        vb = *(const float4*)(emb + (size_t)s_idx[rb] * DEMB + kc * 64 + f * 4);
                    *(float4*)&s_b[r][f * 4] = vb;
                }
                __syncthreads();
#pragma unroll 4
                for (int k4 = 0; k4 < 16; ++k4) {
                    float4 a4[4], b4[4];
#pragma unroll
                    for (int i = 0; i < 4; i++) a4[i] = *(const float4*)&s_a[ty * 4 + i][k4 * 4];
#pragma unroll
                    for (int j = 0; j < 4; j++) b4[j] = *(const float4*)&s_b[tx * 4 + j][k4 * 4];
#pragma unroll
                    for (int i = 0; i < 4; i++)
#pragma unroll
                        for (int j = 0; j < 4; j++)
                            acc[i][j] += a4[i].x * b4[j].x + a4[i].y * b4[j].y +
                                         a4[i].z * b4[j].z + a4[i].w * b4[j].w;
                }
            }

            // reduce this superblock into pos keys
#pragma unroll
            for (int i = 0; i < 4; i++) {
                const int a = sa * 64 + ty * 4 + i;
                if (a >= cnt) break;
                const int ia = s_idx[a];
                const float sqa = g_sq[ia];
                unsigned long long best = 0ull;
#pragma unroll
                for (int j = 0; j < 4; j++) {
                    const int b = sb * 64 + tx * 4 + j;
                    if (b < cnt && b != a) {
                        const int ib = s_idx[b];
                        float d2 = sqa + g_sq[ib] - 2.f * acc[i][j];
                        float d = sqrtf(fmaxf(d2, 0.f));
                        unsigned long long key =
                            ((unsigned long long)__float_as_uint(d) << 32) |
                            (unsigned int)(NPTS - 1 - ib);
                        if (key > best) best = key;
                    }
                }
                if (best) atomicMax(&g_posk[ia], best);
            }
            __syncthreads();
        }
    }
}

// ---------------- phase 0e: extract pos index + dp float -------------------
__global__ void __launch_bounds__(256) posfinal_kernel() {
    int i = blockIdx.x * 256 + threadIdx.x;
    unsigned long long k = g_posk[i];
    g_pos[i] = NPTS - 1 - (int)(k & 0xffffffffu);
    g_dpf[i] = __uint_as_float((unsigned int)(k >> 32));
}

// ---------------- phase B: mma.sync GEMM + fused negative mining -----------
// CTA computes 128x128 tile (by, bx) of the symmetric distance matrix
// (by <= bx), mines hard + semi-hard negatives for both row anchors and
// column anchors (via smem transpose), atomically merges into g_hard/g_semi.
// Inner loop is register-lean: B fragments loaded as hi, consumed by the
// hh + lh terms, then the SAME registers reloaded with lo for the hl term.
__global__ void __launch_bounds__(256) gemm_kernel() {
    extern __shared__ __align__(16) char rawsm[];
    char* dyns = (char*)(((uintptr_t)rawsm + 127) & ~(uintptr_t)127);
    __shared__ float s_sqi[128];
    __shared__ float s_sqj[128];
    __shared__ float s_dpi[128];
    __shared__ float s_dpj[128];
    __shared__ unsigned char s_ti[128];
    __shared__ unsigned char s_tj[128];
    __shared__ unsigned long long s_rh[128], s_rs[128];   // row-anchor hard/semi
    __shared__ unsigned long long s_ch[128], s_cs[128];   // col-anchor hard/semi

    const int tid  = threadIdx.x;
    const int lane = tid & 31;
    const int wid  = tid >> 5;

    // decode triangular tile index
    int t = blockIdx.x;
    int by = 0;
    while (t >= NT - by) { t -= NT - by; by++; }
    const int bx = by + t;
    const int i0 = by * 128;
    const int j0 = bx * 128;

    if (tid < 128) {
        s_sqi[tid] = g_sq[i0 + tid];
        s_dpi[tid] = g_dpf[i0 + tid];
        s_ti[tid]  = g_tgt[i0 + tid];
        s_rh[tid] = ~0ull; s_rs[tid] = ~0ull;
    } else {
        int u = tid - 128;
        s_sqj[u] = g_sq[j0 + u];
        s_dpj[u] = g_dpf[j0 + u];
        s_tj[u]  = g_tgt[j0 + u];
        s_ch[u] = ~0ull; s_cs[u] = ~0ull;
    }

    const int wm = (wid & 3) * 32;   // warp m-offset in CTA tile
    const int wn = (wid >> 2) * 64;  // warp n-offset

    const uint32_t sbase = smem_u32(dyns);

    const int r0l = tid >> 2;            // rows 0..63   (p=0)
    const int r1l = (256 + tid) >> 2;    // rows 64..127 (p=1)
    const int cl  = tid & 3;

    // prologue: stage 0
    {
        uint32_t st = sbase;
#pragma unroll
        for (int p = 0; p < 2; ++p) {
            int r = p ? r1l : r0l;
            uint32_t so = r * 80 + cl * 16;
            size_t ga = (size_t)(i0 + r) * DEMB + cl * 8;
            size_t gb = (size_t)(j0 + r) * DEMB + cl * 8;
            cp16(st + so,         g_hi + ga);
            cp16(st + 10240 + so, g_lo + ga);
            cp16(st + 20480 + so, g_hi + gb);
            cp16(st + 30720 + so, g_lo + gb);
        }
        cp_commit();
    }

    float acc[2][8][4];
#pragma unroll
    for (int a = 0; a < 2; ++a)
#pragma unroll
        for (int b = 0; b < 8; ++b)
#pragma unroll
            for (int c = 0; c < 4; ++c) acc[a][b][c] = 0.f;

    const uint32_t a_row  = (uint32_t)(lane & 15);
    const uint32_t a_coff = (uint32_t)(((lane >> 4) & 1) * 16);
    const uint32_t b_row  = (uint32_t)((lane & 7) + ((lane & 16) >> 1));
    const uint32_t b_coff = (uint32_t)((lane & 8) << 1);

    for (int kc = 0; kc < 32; ++kc) {
        const int cur = kc & 1;
        if (kc + 1 < 32) {
            uint32_t st = sbase + (cur ^ 1) * 40960;
            const int k0 = (kc + 1) * 32;
#pragma unroll
            for (int p = 0; p < 2; ++p) {
                int r = p ? r1l : r0l;
                uint32_t so = r * 80 + cl * 16;
                size_t ga = (size_t)(i0 + r) * DEMB + k0 + cl * 8;
                size_t gb = (size_t)(j0 + r) * DEMB + k0 + cl * 8;
                cp16(st + so,         g_hi + ga);
                cp16(st + 10240 + so, g_lo + ga);
                cp16(st + 20480 + so, g_hi + gb);
                cp16(st + 30720 + so, g_lo + gb);
            }
            cp_commit();
            asm volatile("cp.async.wait_group 1;" ::: "memory");
        } else {
            asm volatile("cp.async.wait_group 0;" ::: "memory");
        }
        __syncthreads();

        const uint32_t st = sbase + cur * 40960;
#pragma unroll
        for (int ks = 0; ks < 2; ++ks) {
            const uint32_t ko = ks * 32;
            uint32_t ah[2][4], al[2][4], bb[4][4];
#pragma unroll
            for (int mf = 0; mf < 2; ++mf) {
                uint32_t rr = (wm + mf * 16 + a_row) * 80 + ko + a_coff;
                ldsm4(st + rr,         ah[mf]);
                ldsm4(st + 10240 + rr, al[mf]);
            }
#pragma unroll
            for (int g = 0; g < 4; ++g) {
                uint32_t rr = (wn + g * 16 + b_row) * 80 + ko + b_coff;
                ldsm4(st + 20480 + rr, bb[g]);
            }
            // hi*hi
#pragma unroll
            for (int mf = 0; mf < 2; ++mf)
#pragma unroll
                for (int nf = 0; nf < 8; ++nf)
                    mma16816(acc[mf][nf], ah[mf], &bb[nf >> 1][(nf & 1) * 2]);
            // lo*hi
#pragma unroll
            for (int mf = 0; mf < 2; ++mf)
#pragma unroll
                for (int nf = 0; nf < 8; ++nf)
                    mma16816(acc[mf][nf], al[mf], &bb[nf >> 1][(nf & 1) * 2]);
            // reload B with lo into the same registers
#pragma unroll
            for (int g = 0; g < 4; ++g) {
                uint32_t rr = (wn + g * 16 + b_row) * 80 + ko + b_coff;
                ldsm4(st + 30720 + rr, bb[g]);
            }
            // hi*lo
#pragma unroll
            for (int mf = 0; mf < 2; ++mf)
#pragma unroll
                for (int nf = 0; nf < 8; ++nf)
                    mma16816(acc[mf][nf], ah[mf], &bb[nf >> 1][(nf & 1) * 2]);
        }
        __syncthreads();
    }

    // ---- epilogue: Gram -> distance --------------------------------------
#pragma unroll
    for (int mf = 0; mf < 2; ++mf) {
#pragma unroll
        for (int rg = 0; rg < 2; ++rg) {
            const int m = wm + mf * 16 + rg * 8 + (lane >> 2);
            const float sqi = s_sqi[m];
#pragma unroll
            for (int nf = 0; nf < 8; ++nf) {
                const int n = wn + nf * 8 + (lane & 3) * 2;
                float d0 = sqi + s_sqj[n]     - 2.f * acc[mf][nf][rg * 2];
                float d1 = sqi + s_sqj[n + 1] - 2.f * acc[mf][nf][rg * 2 + 1];
                acc[mf][nf][rg * 2]     = sqrtf(fmaxf(d0, 0.f));
                acc[mf][nf][rg * 2 + 1] = sqrtf(fmaxf(d1, 0.f));
            }
        }
    }

    // ---- row-anchor mining (from registers) ------------------------------
#pragma unroll
    for (int mf = 0; mf < 2; ++mf) {
#pragma unroll
        for (int rg = 0; rg < 2; ++rg) {
            const int m = wm + mf * 16 + rg * 8 + (lane >> 2);
            const unsigned char tim = s_ti[m];
            const float dpm = s_dpi[m];
            unsigned long long hk = ~0ull, sk = ~0ull;
#pragma unroll
            for (int nf = 0; nf < 8; ++nf) {
#pragma unroll
                for (int cc = 0; cc < 2; ++cc) {
                    const int n = wn + nf * 8 + (lane & 3) * 2 + cc;
                    if (s_tj[n] != tim) {
                        float v = acc[mf][nf][rg * 2 + cc];
                        unsigned long long key =
                            ((unsigned long long)__float_as_uint(v) << 32) |
                            (unsigned int)(j0 + n);
                        if (key < hk) hk = key;
                        if (v > dpm && v < dpm + 1.0f && key < sk) sk = key;
                    }
                }
            }
            if (hk != ~0ull) atomicMin(&s_rh[m], hk);
            if (sk != ~0ull) atomicMin(&s_rs[m], sk);
        }
    }

    // ---- column-anchor mining via smem transpose (off-diagonal only) -----
    if (bx != by) {
        float* stile = (float*)dyns;     // [128][129], reuses pipeline smem
        __syncthreads();
#pragma unroll
        for (int mf = 0; mf < 2; ++mf)
#pragma unroll
            for (int rg = 0; rg < 2; ++rg) {
                const int m = wm + mf * 16 + rg * 8 + (lane >> 2);
#pragma unroll
                for (int nf = 0; nf < 8; ++nf) {
                    const int n = wn + nf * 8 + (lane & 3) * 2;
                    stile[m * 129 + n]     = acc[mf][nf][rg * 2];
                    stile[m * 129 + n + 1] = acc[mf][nf][rg * 2 + 1];
                }
            }
        __syncthreads();
        const int n    = tid >> 1;
        const int half = tid & 1;
        const unsigned char tjn = s_tj[n];
        const float dpn = s_dpj[n];
        unsigned long long hk = ~0ull, sk = ~0ull;
        for (int m = half * 64; m < half * 64 + 64; ++m) {
            if (s_ti[m] != tjn) {
                float v = stile[m * 129 + n];
                unsigned long long key =
                    ((unsigned long long)__float_as_uint(v) << 32) |
                    (unsigned int)(i0 + m);
                if (key < hk) hk = key;
                if (v > dpn && v < dpn + 1.0f && key < sk) sk = key;
            }
        }
        if (hk != ~0ull) atomicMin(&s_ch[n], hk);
        if (sk != ~0ull) atomicMin(&s_cs[n], sk);
    }
    __syncthreads();

    // ---- flush per-CTA results to global ---------------------------------
    if (tid < 128) {
        if (s_rh[tid] != ~0ull) atomicMin(&g_hard[i0 + tid], s_rh[tid]);
        if (s_rs[tid] != ~0ull) atomicMin(&g_semi[i0 + tid], s_rs[tid]);
    } else if (bx != by) {
        int u = tid - 128;
        if (s_ch[u] != ~0ull) atomicMin(&g_hard[j0 + u], s_ch[u]);
        if (s_cs[u] != ~0ull) atomicMin(&g_semi[j0 + u], s_cs[u]);
    }
}

// ---------------- phase D: exact per-anchor loss ---------------------------
__global__ void __launch_bounds__(256) loss_kernel(const float* __restrict__ emb) {
    const int i = blockIdx.x, tid = threadIdx.x;
    unsigned long long skey = g_semi[i];
    unsigned long long hkey = g_hard[i];
    const int pj = g_pos[i];
    const int nj = (skey != ~0ull) ? (int)(skey & 0xffffffffu)
                                   : (int)(hkey & 0xffffffffu);
    const float4* a = (const float4*)(emb + (size_t)i * DEMB);
    const float4* p = (const float4*)(emb + (size_t)pj * DEMB);
    const float4* n = (const float4*)(emb + (size_t)nj * DEMB);
    const float EPSC = 1e-6f;
    float4 av = a[tid], pv = p[tid], nv = n[tid];
    float sp = 0.f, sn = 0.f, t;
    t = av.x - pv.x + EPSC; sp += t * t;
    t = av.y - pv.y + EPSC; sp += t * t;
    t = av.z - pv.z + EPSC; sp += t * t;
    t = av.w - pv.w + EPSC; sp += t * t;
    t = av.x - nv.x + EPSC; sn += t * t;
    t = av.y - nv.y + EPSC; sn += t * t;
    t = av.z - nv.z + EPSC; sn += t * t;
    t = av.w - nv.w + EPSC; sn += t * t;
#pragma unroll
    for (int o = 16; o; o >>= 1) {
        sp += __shfl_down_sync(0xffffffffu, sp, o);
        sn += __shfl_down_sync(0xffffffffu, sn, o);
    }
    __shared__ float rp[8], rn[8];
    const int wid = tid >> 5, lid = tid & 31;
    if (lid == 0) { rp[wid] = sp; rn[wid] = sn; }
    __syncthreads();
    if (tid == 0) {
        float SP = 0.f, SN = 0.f;
#pragma unroll
        for (int w = 0; w < 8; w++) { SP += rp[w]; SN += rn[w]; }
        g_loss[i] = fmaxf(0.f, sqrtf(SP) - sqrtf(SN) + 1.0f);
    }
}

// ---------------- final: deterministic mean --------------------------------
__global__ void __launch_bounds__(256) reduce_kernel(float* __restrict__ out) {
    __shared__ float sb[256];
    const int tid = threadIdx.x;
    float s = 0.f;
    for (int j = tid; j < NPTS; j += 256) s += g_loss[j];
    sb[tid] = s; __syncthreads();
    for (int k = 128; k; k >>= 1) {
        if (tid < k) sb[tid] += sb[tid + k];
        __syncthreads();
    }
    if (tid == 0) out[0] = sb[0] / (float)NPTS;
}

// ---------------- launch ----------------------------------------------------
extern "C" void kernel_launch(void* const* d_in, const int* in_sizes, int n_in,
                              void* d_out, int out_size) {
    const float* emb = (const float*)d_in[0];
    const int*   tgt = (const int*)d_in[1];
    float*       out = (float*)d_out;

    cudaFuncSetAttribute(gemm_kernel, cudaFuncAttributeMaxDynamicSharedMemorySize, 82048);

    conv_kernel<<<(NPTS * DEMB) / 256, 256>>>(emb);        // 1
    sq_kernel<<<NPTS / 8, 256>>>(emb, tgt);                // 2
    clsbuild_kernel<<<NPTS / 256, 256>>>(tgt);             // 3
    posmine_kernel<<<NCLS, 256>>>(emb);                    // 4
    posfinal_kernel<<<NPTS / 256, 256>>>();                // 5
    gemm_kernel<<<NTILES, 256, 82048>>>();                 // 6  <- ncu capture
    loss_kernel<<<NPTS, 256>>>(emb);                       // 7
    reduce_kernel<<<1, 256>>>(out);                        // 8
}

// round 12
// speedup vs baseline: 1.7844x; 1.7844x over previous
#include <cuda_runtime.h>
#include <cuda_bf16.h>
#include <cstdint>
#include <math.h>

#define NPTS 8192
#define DEMB 1024
#define NT   64            // 128-wide tiles per dim
#define NTILES 2080        // NT*(NT+1)/2 upper-triangular tiles
#define NCLS  128
#define CCAP  256          // class list capacity

// ---------------- scratch (device globals: no allocations allowed) ----------
__device__ __align__(128) __nv_bfloat16 g_hi[(size_t)NPTS * DEMB];   // 16 MB
__device__ __align__(128) __nv_bfloat16 g_lo[(size_t)NPTS * DEMB];   // 16 MB
__device__ __align__(128) float         g_sq[NPTS];
__device__ __align__(128) unsigned char g_tgt[NPTS];
__device__ __align__(128) int           g_ccnt[NCLS];
__device__ __align__(128) int           g_clist[NCLS * CCAP];
__device__ __align__(128) unsigned long long g_posk[NPTS];
__device__ __align__(128) unsigned long long g_hard[NPTS];
__device__ __align__(128) unsigned long long g_semi[NPTS];
__device__ __align__(128) float         g_loss[NPTS];

// ---------------- ptx helpers ----------------------------------------------
__device__ __forceinline__ uint32_t smem_u32(const void* p) {
    uint32_t a;
    asm("{ .reg .u64 t; cvta.to.shared.u64 t, %1; cvt.u32.u64 %0, t; }"
        : "=r"(a) : "l"(p));
    return a;
}

__device__ __forceinline__ void cp16(uint32_t s, const void* g) {
    asm volatile("cp.async.cg.shared.global [%0], [%1], 16;" :: "r"(s), "l"(g));
}
__device__ __forceinline__ void cp_commit() {
    asm volatile("cp.async.commit_group;" ::: "memory");
}

__device__ __forceinline__ void ldsm4(uint32_t addr, uint32_t* r) {
    asm volatile("ldmatrix.sync.aligned.m8n8.x4.shared.b16 {%0,%1,%2,%3}, [%4];"
        : "=r"(r[0]), "=r"(r[1]), "=r"(r[2]), "=r"(r[3]) : "r"(addr));
}

__device__ __forceinline__ void mma16816(float* c, const uint32_t* a, const uint32_t* b) {
    asm volatile(
        "mma.sync.aligned.m16n8k16.row.col.f32.bf16.bf16.f32 "
        "{%0,%1,%2,%3},{%4,%5,%6,%7},{%8,%9},{%0,%1,%2,%3};"
        : "+f"(c[0]), "+f"(c[1]), "+f"(c[2]), "+f"(c[3])
        : "r"(a[0]), "r"(a[1]), "r"(a[2]), "r"(a[3]), "r"(b[0]), "r"(b[1]));
}

// ---------------- phase 1: fused convert(hi/lo) + row norms + tgt ----------
__global__ void __launch_bounds__(256) convsq_kernel(const float* __restrict__ emb,
                                                     const int* __restrict__ tgt) {
    if (blockIdx.x == 0 && threadIdx.x < NCLS) g_ccnt[threadIdx.x] = 0;
    const int row = blockIdx.x * 8 + (threadIdx.x >> 5);
    const int lid = threadIdx.x & 31;
    const float4* r4 = (const float4*)(emb + (size_t)row * DEMB);
    float s = 0.f;
#pragma unroll
    for (int k = 0; k < 8; k++) {
        const int e = lid + k * 32;
        float4 v = r4[e];
        s += v.x * v.x + v.y * v.y + v.z * v.z + v.w * v.w;
        __nv_bfloat16 hx = __float2bfloat16(v.x), hy = __float2bfloat16(v.y);
        __nv_bfloat16 hz = __float2bfloat16(v.z), hw = __float2bfloat16(v.w);
        __nv_bfloat162* ph = (__nv_bfloat162*)(g_hi + (size_t)row * DEMB + e * 4);
        ph[0] = __nv_bfloat162(hx, hy);
        ph[1] = __nv_bfloat162(hz, hw);
        __nv_bfloat162* pl = (__nv_bfloat162*)(g_lo + (size_t)row * DEMB + e * 4);
        pl[0] = __nv_bfloat162(__float2bfloat16(v.x - __bfloat162float(hx)),
                               __float2bfloat16(v.y - __bfloat162float(hy)));
        pl[1] = __nv_bfloat162(__float2bfloat16(v.z - __bfloat162float(hz)),
                               __float2bfloat16(v.w - __bfloat162float(hw)));
    }
#pragma unroll
    for (int o = 16; o; o >>= 1) s += __shfl_down_sync(0xffffffffu, s, o);
    if (lid == 0) {
        g_sq[row] = s;
        g_tgt[row] = (unsigned char)tgt[row];
    }
}

// ---------------- phase 2: class lists + key init ---------------------------
__global__ void __launch_bounds__(256) clsbuild_kernel(const int* __restrict__ tgt) {
    int i = blockIdx.x * 256 + threadIdx.x;
    g_posk[i] = 0ull;
    g_hard[i] = ~0ull;
    g_semi[i] = ~0ull;
    int c = tgt[i];
    int p = atomicAdd(&g_ccnt[c], 1);
    if (p < CCAP) g_clist[c * CCAP + p] = i;
}

// ---------------- phase 3: hardest positive via one mma tile per class -----
// One CTA per class: gather up to 128 member rows (hi/lo), compute the
// 128x128 same-class Gram with the same 3-term bf16 split as the main GEMM
// (A == B: one smem copy), mine per-anchor max-distance key.
// key = (bits(d)<<32) | (NPTS-1-j): max key = max d, min j on tie.
__global__ void __launch_bounds__(256) posmine_kernel() {
    extern __shared__ __align__(16) char rawsm[];
    char* dyns = (char*)(((uintptr_t)rawsm + 127) & ~(uintptr_t)127);
    __shared__ int   s_idx[128];
    __shared__ float s_sq[128];
    __shared__ unsigned long long s_pk[128];

    const int tid  = threadIdx.x;
    const int lane = tid & 31;
    const int wid  = tid >> 5;
    const int c    = blockIdx.x;

    int cnt = g_ccnt[c];
    if (cnt > 128) cnt = 128;
    if (tid < 128) {
        int gi = g_clist[c * CCAP + (tid < cnt ? tid : 0)];
        s_idx[tid] = gi;
        s_sq[tid]  = g_sq[gi];
        s_pk[tid]  = 0ull;
    }
    __syncthreads();

    const int wm = (wid & 3) * 32;
    const int wn = (wid >> 2) * 64;
    const uint32_t sbase = smem_u32(dyns);   // stage: hi @0 (10240), lo @10240; x2 stages stride 20480

    const int r0l = tid >> 2;
    const int r1l = (256 + tid) >> 2;
    const int cl  = tid & 3;

    {   // prologue stage 0
        uint32_t st = sbase;
#pragma unroll
        for (int p = 0; p < 2; ++p) {
            int r = p ? r1l : r0l;
            uint32_t so = r * 80 + cl * 16;
            size_t ga = (size_t)s_idx[r] * DEMB + cl * 8;
            cp16(st + so,         g_hi + ga);
            cp16(st + 10240 + so, g_lo + ga);
        }
        cp_commit();
    }

    float acc[2][8][4];
#pragma unroll
    for (int a = 0; a < 2; ++a)
#pragma unroll
        for (int b = 0; b < 8; ++b)
#pragma unroll
            for (int q = 0; q < 4; ++q) acc[a][b][q] = 0.f;

    const uint32_t a_row  = (uint32_t)(lane & 15);
    const uint32_t a_coff = (uint32_t)(((lane >> 4) & 1) * 16);
    const uint32_t b_row  = (uint32_t)((lane & 7) + ((lane & 16) >> 1));
    const uint32_t b_coff = (uint32_t)((lane & 8) << 1);

    for (int kc = 0; kc < 32; ++kc) {
        const int cur = kc & 1;
        if (kc + 1 < 32) {
            uint32_t st = sbase + (cur ^ 1) * 20480;
            const int k0 = (kc + 1) * 32;
#pragma unroll
            for (int p = 0; p < 2; ++p) {
                int r = p ? r1l : r0l;
                uint32_t so = r * 80 + cl * 16;
                size_t ga = (size_t)s_idx[r] * DEMB + k0 + cl * 8;
                cp16(st + so,         g_hi + ga);
                cp16(st + 10240 + so, g_lo + ga);
            }
            cp_commit();
            asm volatile("cp.async.wait_group 1;" ::: "memory");
        } else {
            asm volatile("cp.async.wait_group 0;" ::: "memory");
        }
        __syncthreads();

        const uint32_t st = sbase + cur * 20480;
#pragma unroll
        for (int ks = 0; ks < 2; ++ks) {
            const uint32_t ko = ks * 32;
            uint32_t ah[2][4], al[2][4], bb[4][4];
#pragma unroll
            for (int mf = 0; mf < 2; ++mf) {
                uint32_t rr = (wm + mf * 16 + a_row) * 80 + ko + a_coff;
                ldsm4(st + rr,         ah[mf]);
                ldsm4(st + 10240 + rr, al[mf]);
            }
#pragma unroll
            for (int g = 0; g < 4; ++g) {
                uint32_t rr = (wn + g * 16 + b_row) * 80 + ko + b_coff;
                ldsm4(st + rr, bb[g]);           // B = hi (same buffer as A)
            }
#pragma unroll
            for (int mf = 0; mf < 2; ++mf)
#pragma unroll
                for (int nf = 0; nf < 8; ++nf)
                    mma16816(acc[mf][nf], ah[mf], &bb[nf >> 1][(nf & 1) * 2]);
#pragma unroll
            for (int mf = 0; mf < 2; ++mf)
#pragma unroll
                for (int nf = 0; nf < 8; ++nf)
                    mma16816(acc[mf][nf], al[mf], &bb[nf >> 1][(nf & 1) * 2]);
#pragma unroll
            for (int g = 0; g < 4; ++g) {
                uint32_t rr = (wn + g * 16 + b_row) * 80 + ko + b_coff;
                ldsm4(st + 10240 + rr, bb[g]);   // reload B = lo
            }
#pragma unroll
            for (int mf = 0; mf < 2; ++mf)
#pragma unroll
                for (int nf = 0; nf < 8; ++nf)
                    mma16816(acc[mf][nf], ah[mf], &bb[nf >> 1][(nf & 1) * 2]);
        }
        __syncthreads();
    }

    // mine hardest positive per row
#pragma unroll
    for (int mf = 0; mf < 2; ++mf) {
#pragma unroll
        for (int rg = 0; rg < 2; ++rg) {
            const int m = wm + mf * 16 + rg * 8 + (lane >> 2);
            if (m >= cnt) continue;
            const float sqi = s_sq[m];
            unsigned long long best = 0ull;
#pragma unroll
            for (int nf = 0; nf < 8; ++nf) {
#pragma unroll
                for (int cc = 0; cc < 2; ++cc) {
                    const int n = wn + nf * 8 + (lane & 3) * 2 + cc;
                    if (n < cnt && n != m) {
                        float d2 = sqi + s_sq[n] - 2.f * acc[mf][nf][rg * 2 + cc];
                        float d = sqrtf(fmaxf(d2, 0.f));
                        unsigned long long key =
                            ((unsigned long long)__float_as_uint(d) << 32) |
                            (unsigned int)(NPTS - 1 - s_idx[n]);
                        if (key > best) best = key;
                    }
                }
            }
            if (best) atomicMax(&s_pk[m], best);
        }
    }
    __syncthreads();
    if (tid < cnt) g_posk[s_idx[tid]] = s_pk[tid];
}

// ---------------- phase 4: mma.sync GEMM + fused negative mining -----------
// CTA computes 128x128 tile (by, bx), by <= bx, of the symmetric distance
// matrix; mines hard + semi-hard negatives for row anchors and (off-diag)
// column anchors via smem transpose; merges keys into g_hard/g_semi.
// minBlocksPerMultiprocessor=2 caps regs at 128 so 2 CTAs/SM co-reside.
__global__ void __launch_bounds__(256, 2) gemm_kernel() {
    extern __shared__ __align__(16) char rawsm[];
    char* dyns = (char*)(((uintptr_t)rawsm + 127) & ~(uintptr_t)127);
    __shared__ float s_sqi[128];
    __shared__ float s_sqj[128];
    __shared__ float s_dpi[128];
    __shared__ float s_dpj[128];
    __shared__ unsigned char s_ti[128];
    __shared__ unsigned char s_tj[128];
    __shared__ unsigned long long s_rh[128], s_rs[128];
    __shared__ unsigned long long s_ch[128], s_cs[128];

    const int tid  = threadIdx.x;
    const int lane = tid & 31;
    const int wid  = tid >> 5;

    int t = blockIdx.x;
    int by = 0;
    while (t >= NT - by) { t -= NT - by; by++; }
    const int bx = by + t;
    const int i0 = by * 128;
    const int j0 = bx * 128;

    if (tid < 128) {
        s_sqi[tid] = g_sq[i0 + tid];
        s_dpi[tid] = __uint_as_float((unsigned int)(g_posk[i0 + tid] >> 32));
        s_ti[tid]  = g_tgt[i0 + tid];
        s_rh[tid] = ~0ull; s_rs[tid] = ~0ull;
    } else {
        int u = tid - 128;
        s_sqj[u] = g_sq[j0 + u];
        s_dpj[u] = __uint_as_float((unsigned int)(g_posk[j0 + u] >> 32));
        s_tj[u]  = g_tgt[j0 + u];
        s_ch[u] = ~0ull; s_cs[u] = ~0ull;
    }

    const int wm = (wid & 3) * 32;
    const int wn = (wid >> 2) * 64;
    const uint32_t sbase = smem_u32(dyns);

    const int r0l = tid >> 2;
    const int r1l = (256 + tid) >> 2;
    const int cl  = tid & 3;

    {   // prologue stage 0
        uint32_t st = sbase;
#pragma unroll
        for (int p = 0; p < 2; ++p) {
            int r = p ? r1l : r0l;
            uint32_t so = r * 80 + cl * 16;
            size_t ga = (size_t)(i0 + r) * DEMB + cl * 8;
            size_t gb = (size_t)(j0 + r) * DEMB + cl * 8;
            cp16(st + so,         g_hi + ga);
            cp16(st + 10240 + so, g_lo + ga);
            cp16(st + 20480 + so, g_hi + gb);
            cp16(st + 30720 + so, g_lo + gb);
        }
        cp_commit();
    }

    float acc[2][8][4];
#pragma unroll
    for (int a = 0; a < 2; ++a)
#pragma unroll
        for (int b = 0; b < 8; ++b)
#pragma unroll
            for (int q = 0; q < 4; ++q) acc[a][b][q] = 0.f;

    const uint32_t a_row  = (uint32_t)(lane & 15);
    const uint32_t a_coff = (uint32_t)(((lane >> 4) & 1) * 16);
    const uint32_t b_row  = (uint32_t)((lane & 7) + ((lane & 16) >> 1));
    const uint32_t b_coff = (uint32_t)((lane & 8) << 1);

    for (int kc = 0; kc < 32; ++kc) {
        const int cur = kc & 1;
        if (kc + 1 < 32) {
            uint32_t st = sbase + (cur ^ 1) * 40960;
            const int k0 = (kc + 1) * 32;
#pragma unroll
            for (int p = 0; p < 2; ++p) {
                int r = p ? r1l : r0l;
                uint32_t so = r * 80 + cl * 16;
                size_t ga = (size_t)(i0 + r) * DEMB + k0 + cl * 8;
                size_t gb = (size_t)(j0 + r) * DEMB + k0 + cl * 8;
                cp16(st + so,         g_hi + ga);
                cp16(st + 10240 + so, g_lo + ga);
                cp16(st + 20480 + so, g_hi + gb);
                cp16(st + 30720 + so, g_lo + gb);
            }
            cp_commit();
            asm volatile("cp.async.wait_group 1;" ::: "memory");
        } else {
            asm volatile("cp.async.wait_group 0;" ::: "memory");
        }
        __syncthreads();

        const uint32_t st = sbase + cur * 40960;
#pragma unroll
        for (int ks = 0; ks < 2; ++ks) {
            const uint32_t ko = ks * 32;
            uint32_t ah[2][4], al[2][4], bb[4][4];
#pragma unroll
            for (int mf = 0; mf < 2; ++mf) {
                uint32_t rr = (wm + mf * 16 + a_row) * 80 + ko + a_coff;
                ldsm4(st + rr,         ah[mf]);
                ldsm4(st + 10240 + rr, al[mf]);
            }
#pragma unroll
            for (int g = 0; g < 4; ++g) {
                uint32_t rr = (wn + g * 16 + b_row) * 80 + ko + b_coff;
                ldsm4(st + 20480 + rr, bb[g]);
            }
#pragma unroll
            for (int mf = 0; mf < 2; ++mf)
#pragma unroll
                for (int nf = 0; nf < 8; ++nf)
                    mma16816(acc[mf][nf], ah[mf], &bb[nf >> 1][(nf & 1) * 2]);
#pragma unroll
            for (int mf = 0; mf < 2; ++mf)
#pragma unroll
                for (int nf = 0; nf < 8; ++nf)
                    mma16816(acc[mf][nf], al[mf], &bb[nf >> 1][(nf & 1) * 2]);
#pragma unroll
            for (int g = 0; g < 4; ++g) {
                uint32_t rr = (wn + g * 16 + b_row) * 80 + ko + b_coff;
                ldsm4(st + 30720 + rr, bb[g]);
            }
#pragma unroll
            for (int mf = 0; mf < 2; ++mf)
#pragma unroll
                for (int nf = 0; nf < 8; ++nf)
                    mma16816(acc[mf][nf], ah[mf], &bb[nf >> 1][(nf & 1) * 2]);
        }
        __syncthreads();
    }

    // ---- epilogue: Gram -> distance --------------------------------------
#pragma unroll
    for (int mf = 0; mf < 2; ++mf) {
#pragma unroll
        for (int rg = 0; rg < 2; ++rg) {
            const int m = wm + mf * 16 + rg * 8 + (lane >> 2);
            const float sqi = s_sqi[m];
#pragma unroll
            for (int nf = 0; nf < 8; ++nf) {
                const int n = wn + nf * 8 + (lane & 3) * 2;
                float d0 = sqi + s_sqj[n]     - 2.f * acc[mf][nf][rg * 2];
                float d1 = sqi + s_sqj[n + 1] - 2.f * acc[mf][nf][rg * 2 + 1];
                acc[mf][nf][rg * 2]     = sqrtf(fmaxf(d0, 0.f));
                acc[mf][nf][rg * 2 + 1] = sqrtf(fmaxf(d1, 0.f));
            }
        }
    }

    // ---- row-anchor mining (from registers) ------------------------------
#pragma unroll
    for (int mf = 0; mf < 2; ++mf) {
#pragma unroll
        for (int rg = 0; rg < 2; ++rg) {
            const int m = wm + mf * 16 + rg * 8 + (lane >> 2);
            const unsigned char tim = s_ti[m];
            const float dpm = s_dpi[m];
            unsigned long long hk = ~0ull, sk = ~0ull;
#pragma unroll
            for (int nf = 0; nf < 8; ++nf) {
#pragma unroll
                for (int cc = 0; cc < 2; ++cc) {
                    const int n = wn + nf * 8 + (lane & 3) * 2 + cc;
                    if (s_tj[n] != tim) {
                        float v = acc[mf][nf][rg * 2 + cc];
                        unsigned long long key =
                            ((unsigned long long)__float_as_uint(v) << 32) |
                            (unsigned int)(j0 + n);
                        if (key < hk) hk = key;
                        if (v > dpm && v < dpm + 1.0f && key < sk) sk = key;
                    }
                }
            }
            if (hk != ~0ull) atomicMin(&s_rh[m], hk);
            if (sk != ~0ull) atomicMin(&s_rs[m], sk);
        }
    }

    // ---- column-anchor mining via smem transpose (off-diagonal only) -----
    if (bx != by) {
        float* stile = (float*)dyns;     // [128][129], reuses pipeline smem
        __syncthreads();
#pragma unroll
        for (int mf = 0; mf < 2; ++mf)
#pragma unroll
            for (int rg = 0; rg < 2; ++rg) {
                const int m = wm + mf * 16 + rg * 8 + (lane >> 2);
#pragma unroll
                for (int nf = 0; nf < 8; ++nf) {
                    const int n = wn + nf * 8 + (lane & 3) * 2;
                    stile[m * 129 + n]     = acc[mf][nf][rg * 2];
                    stile[m * 129 + n + 1] = acc[mf][nf][rg * 2 + 1];
                }
            }
        __syncthreads();
        const int n    = tid >> 1;
        const int half = tid & 1;
        const unsigned char tjn = s_tj[n];
        const float dpn = s_dpj[n];
        unsigned long long hk = ~0ull, sk = ~0ull;
        for (int m = half * 64; m < half * 64 + 64; ++m) {
            if (s_ti[m] != tjn) {
                float v = stile[m * 129 + n];
                unsigned long long key =
                    ((unsigned long long)__float_as_uint(v) << 32) |
                    (unsigned int)(i0 + m);
                if (key < hk) hk = key;
                if (v > dpn && v < dpn + 1.0f && key < sk) sk = key;
            }
        }
        if (hk != ~0ull) atomicMin(&s_ch[n], hk);
        if (sk != ~0ull) atomicMin(&s_cs[n], sk);
    }
    __syncthreads();

    // ---- flush per-CTA results to global ---------------------------------
    if (tid < 128) {
        if (s_rh[tid] != ~0ull) atomicMin(&g_hard[i0 + tid], s_rh[tid]);
        if (s_rs[tid] != ~0ull) atomicMin(&g_semi[i0 + tid], s_rs[tid]);
    } else if (bx != by) {
        int u = tid - 128;
        if (s_ch[u] != ~0ull) atomicMin(&g_hard[j0 + u], s_ch[u]);
        if (s_cs[u] != ~0ull) atomicMin(&g_semi[j0 + u], s_cs[u]);
    }
}

// ---------------- phase 5: exact per-anchor loss ---------------------------
__global__ void __launch_bounds__(256) loss_kernel(const float* __restrict__ emb) {
    const int i = blockIdx.x, tid = threadIdx.x;
    unsigned long long skey = g_semi[i];
    unsigned long long hkey = g_hard[i];
    const int pj = NPTS - 1 - (int)(g_posk[i] & 0xffffffffu);
    const int nj = (skey != ~0ull) ? (int)(skey & 0xffffffffu)
                                   : (int)(hkey & 0xffffffffu);
    const float4* a = (const float4*)(emb + (size_t)i * DEMB);
    const float4* p = (const float4*)(emb + (size_t)pj * DEMB);
    const float4* n = (const float4*)(emb + (size_t)nj * DEMB);
    const float EPSC = 1e-6f;
    float4 av = a[tid], pv = p[tid], nv = n[tid];
    float sp = 0.f, sn = 0.f, t;
    t = av.x - pv.x + EPSC; sp += t * t;
    t = av.y - pv.y + EPSC; sp += t * t;
    t = av.z - pv.z + EPSC; sp += t * t;
    t = av.w - pv.w + EPSC; sp += t * t;
    t = av.x - nv.x + EPSC; sn += t * t;
    t = av.y - nv.y + EPSC; sn += t * t;
    t = av.z - nv.z + EPSC; sn += t * t;
    t = av.w - nv.w + EPSC; sn += t * t;
#pragma unroll
    for (int o = 16; o; o >>= 1) {
        sp += __shfl_down_sync(0xffffffffu, sp, o);
        sn += __shfl_down_sync(0xffffffffu, sn, o);
    }
    __shared__ float rp[8], rn[8];
    const int wid = tid >> 5, lid = tid & 31;
    if (lid == 0) { rp[wid] = sp; rn[wid] = sn; }
    __syncthreads();
    if (tid == 0) {
        float SP = 0.f, SN = 0.f;
#pragma unroll
        for (int w = 0; w < 8; w++) { SP += rp[w]; SN += rn[w]; }
        g_loss[i] = fmaxf(0.f, sqrtf(SP) - sqrtf(SN) + 1.0f);
    }
}

// ---------------- final: deterministic mean --------------------------------
__global__ void __launch_bounds__(256) reduce_kernel(float* __restrict__ out) {
    __shared__ float sb[256];
    const int tid = threadIdx.x;
    float s = 0.f;
    for (int j = tid; j < NPTS; j += 256) s += g_loss[j];
    sb[tid] = s; __syncthreads();
    for (int k = 128; k; k >>= 1) {
        if (tid < k) sb[tid] += sb[tid + k];
        __syncthreads();
    }
    if (tid == 0) out[0] = sb[0] / (float)NPTS;
}

// ---------------- launch ----------------------------------------------------
extern "C" void kernel_launch(void* const* d_in, const int* in_sizes, int n_in,
                              void* d_out, int out_size) {
    const float* emb = (const float*)d_in[0];
    const int*   tgt = (const int*)d_in[1];
    float*       out = (float*)d_out;

    cudaFuncSetAttribute(gemm_kernel, cudaFuncAttributeMaxDynamicSharedMemorySize, 82048);

    convsq_kernel<<<NPTS / 8, 256>>>(emb, tgt);            // 1
    clsbuild_kernel<<<NPTS / 256, 256>>>(tgt);             // 2
    posmine_kernel<<<NCLS, 256, 41088>>>();                // 3
    gemm_kernel<<<NTILES, 256, 82048>>>();                 // 4  <- ncu capture
    loss_kernel<<<NPTS, 256>>>(emb);                       // 5
    reduce_kernel<<<1, 256>>>(out);                        // 6
}